// round 11
// baseline (speedup 1.0000x reference)
#include <cuda_runtime.h>
#include <math.h>

constexpr int C   = 32;
constexpr int N_H = 40000, D_H = 16;
constexpr int N_O = 20000, D_O = 48;

constexpr int WPB   = 8;
constexpr int BLOCK = WPB * 32;          // 256 threads, warp = 1 atom
constexpr int NB_O  = N_O / WPB;         // 2500
constexpr int NB_H  = N_H / WPB;         // 5000
constexpr int NB    = NB_O + NB_H;       // 7500; bid%3==0 -> O else H

typedef unsigned long long u64;

// ---- packed f32x2 helpers (Blackwell FFMA2 path, PTX-only) ----
__device__ __forceinline__ u64 fma2(u64 a, u64 b, u64 c) {
    u64 d;
    asm("fma.rn.f32x2 %0, %1, %2, %3;" : "=l"(d) : "l"(a), "l"(b), "l"(c));
    return d;
}
__device__ __forceinline__ u64 add2(u64 a, u64 b) {
    u64 d;
    asm("add.rn.f32x2 %0, %1, %2;" : "=l"(d) : "l"(a), "l"(b));
    return d;
}
__device__ __forceinline__ u64 mul2(u64 a, u64 b) {
    u64 d;
    asm("mul.rn.f32x2 %0, %1, %2;" : "=l"(d) : "l"(a), "l"(b));
    return d;
}
__device__ __forceinline__ u64 pack2(float lo, float hi) {
    u64 d;
    asm("mov.b64 %0, {%1, %2};" : "=l"(d) : "r"(__float_as_uint(lo)), "r"(__float_as_uint(hi)));
    return d;
}
__device__ __forceinline__ void unpack2(u64 v, float& lo, float& hi) {
    unsigned int a, b;
    asm("mov.b64 {%0, %1}, %2;" : "=r"(a), "=r"(b) : "l"(v));
    lo = __uint_as_float(a);
    hi = __uint_as_float(b);
}

// Folded lower-triangular S, row i padded to a multiple of 4 floats (zeros).
__host__ __device__ constexpr int rowLen(int i) { return (i + 4) & ~3; }
__host__ __device__ constexpr int rowOff(int i) {
    int s = 0;
    for (int t = 0; t < i; t++) s += rowLen(t);
    return s;
}
template <int D>
__host__ __device__ constexpr int triTot() { return rowOff(D); }
// D=48 -> 1248 floats, D=16 -> 160 floats

// Compile-time row-offset table, resident in constant memory (no per-block
// divides or offset recomputation).
struct OffTab { int off[D_O]; };
__host__ __device__ constexpr OffTab makeOffTab() {
    OffTab t{};
    int s = 0;
    for (int i = 0; i < D_O; i++) { t.off[i] = s; s += rowLen(i); }
    return t;
}
__constant__ OffTab c_off = makeOffTab();

// Row-per-thread fill: thread i copies lower-tri row i (scaled), zeros pads.
template <int D>
__device__ __forceinline__ void fillS(const float* __restrict__ S, float* Sp) {
    const int i = threadIdx.x;
    if (i < D) {
        const int off = c_off.off[i];
        for (int j = 0; j < i; j++) Sp[off + j] = 2.0f * __ldg(S + i * D + j);
        Sp[off + i] = __ldg(S + i * D + i);
        for (int j = i + 1; j < rowLen(i); j++) Sp[off + j] = 0.0f;
    }
    __syncthreads();
}

// Warp = 1 atom, lane = channel; rows packed in pairs into u64.
// Even/odd-row chunk loops are sequential (keeps live set small -> 64 regs);
// dual accumulators break the outer dependency chain.
template <int D>
__device__ __forceinline__ void processAtom(const float* __restrict__ x,
                                            float* __restrict__ out,
                                            const float* __restrict__ Sp,
                                            int baseRow, int lane) {
    constexpr int KP = D / 2;
    const float* xp = x + (size_t)baseRow * C + lane;

    u64 y2[KP];
#pragma unroll
    for (int k = 0; k < KP; k++) {
        float a = __ldg(xp + (2 * k + 0) * C);
        float b = __ldg(xp + (2 * k + 1) * C);
        y2[k] = pack2(a, b);
    }

    u64 accA = 0ull, accB = 0ull;
#pragma unroll
    for (int k = 0; k < KP; k++) {
        const int i0 = 2 * k;
        const int nc = k / 2 + 1;  // float4 chunks per row of the pair
        const ulonglong2* r0 = reinterpret_cast<const ulonglong2*>(Sp + rowOff(i0));
        const ulonglong2* r1 = reinterpret_cast<const ulonglong2*>(Sp + rowOff(i0 + 1));

        // even row 2k
        u64 e0 = 0ull, e1 = 0ull;
#pragma unroll
        for (int jc = 0; jc < nc; jc++) {
            ulonglong2 a = r0[jc];  // LDS.128 broadcast: 4 folded-S values
            e0 = fma2(a.x, y2[2 * jc + 0], e0);
            e1 = fma2(a.y, y2[2 * jc + 1], e1);
        }
        float el, eh;
        unpack2(add2(e0, e1), el, eh);

        // odd row 2k+1
        u64 o0 = 0ull, o1 = 0ull;
#pragma unroll
        for (int jc = 0; jc < nc; jc++) {
            ulonglong2 b = r1[jc];
            o0 = fma2(b.x, y2[2 * jc + 0], o0);
            o1 = fma2(b.y, y2[2 * jc + 1], o1);
        }
        float ol, oh;
        unpack2(add2(o0, o1), ol, oh);

        if (k & 1)
            accB = fma2(y2[k], pack2(el + eh, ol + oh), accB);
        else
            accA = fma2(y2[k], pack2(el + eh, ol + oh), accA);
    }

    float alo, ahi;
    unpack2(add2(accA, accB), alo, ahi);
    const float inv  = 1.0f / (sqrtf(alo + ahi) + 1e-6f);
    const u64   inv2 = pack2(inv, inv);

    float* op = out + (size_t)baseRow * C + lane;
#pragma unroll
    for (int k = 0; k < KP; k++) {
        u64 m = mul2(y2[k], inv2);
        float s0, s1;
        unpack2(m, s0, s1);
        op[(2 * k + 0) * C] = s0;
        op[(2 * k + 1) * C] = s1;
    }
}

// Fused kernel: every 3rd block is an O block, the other two are H blocks,
// pinning a ~1:2 O:H mix per SM (L1-bound O work overlaps DRAM-bound H work).
__global__ __launch_bounds__(BLOCK, 4) void l2norm_fused(
    const float* __restrict__ x,
    const float* __restrict__ S_H, const float* __restrict__ S_O,
    const int* __restrict__ idx_H, const int* __restrict__ idx_O,
    float* __restrict__ out) {
    __shared__ __align__(16) float Sp[triTot<D_O>()];

    const int warp = threadIdx.x >> 5;
    const int lane = threadIdx.x & 31;
    const int bid  = blockIdx.x;
    const int q    = bid / 3;        // O block index if bid%3==0
    const int r    = bid - 3 * q;    // bid % 3

    if (r == 0) {
        fillS<D_O>(S_O, Sp);
        const int atom = q * WPB + warp;
        const int baseRow = __ldg(idx_O + atom * D_O);
        processAtom<D_O>(x, out, Sp, baseRow, lane);
    } else {
        fillS<D_H>(S_H, Sp);
        const int atom = (2 * q + (r - 1)) * WPB + warp;  // 0..NB_H-1
        const int baseRow = __ldg(idx_H + atom * D_H);
        processAtom<D_H>(x, out, Sp, baseRow, lane);
    }
}

extern "C" void kernel_launch(void* const* d_in, const int* in_sizes, int n_in,
                              void* d_out, int out_size) {
    const float* x     = (const float*)d_in[0];
    const float* S_H   = (const float*)d_in[1];
    const float* S_O   = (const float*)d_in[2];
    const int*   idx_H = (const int*)d_in[3];
    const int*   idx_O = (const int*)d_in[4];
    float* out = (float*)d_out;

    l2norm_fused<<<NB, BLOCK>>>(x, S_H, S_O, idx_H, idx_O, out);
}

// round 12
// speedup vs baseline: 1.2484x; 1.2484x over previous
#include <cuda_runtime.h>
#include <math.h>

constexpr int C   = 32;
constexpr int N_H = 40000, D_H = 16;
constexpr int N_O = 20000, D_O = 48;

constexpr int WPB   = 8;
constexpr int BLOCK = WPB * 32;          // 256 threads, warp = 1 atom
constexpr int NB_O  = N_O / WPB;         // 2500
constexpr int NB_H  = N_H / WPB;         // 5000
constexpr int NB    = NB_O + NB_H;       // 7500; bid%3==0 -> O else H

typedef unsigned long long u64;

// ---- packed f32x2 helpers (Blackwell FFMA2 path, PTX-only) ----
__device__ __forceinline__ u64 fma2(u64 a, u64 b, u64 c) {
    u64 d;
    asm("fma.rn.f32x2 %0, %1, %2, %3;" : "=l"(d) : "l"(a), "l"(b), "l"(c));
    return d;
}
__device__ __forceinline__ u64 add2(u64 a, u64 b) {
    u64 d;
    asm("add.rn.f32x2 %0, %1, %2;" : "=l"(d) : "l"(a), "l"(b));
    return d;
}
__device__ __forceinline__ u64 mul2(u64 a, u64 b) {
    u64 d;
    asm("mul.rn.f32x2 %0, %1, %2;" : "=l"(d) : "l"(a), "l"(b));
    return d;
}
__device__ __forceinline__ u64 pack2(float lo, float hi) {
    u64 d;
    asm("mov.b64 %0, {%1, %2};" : "=l"(d) : "r"(__float_as_uint(lo)), "r"(__float_as_uint(hi)));
    return d;
}
__device__ __forceinline__ void unpack2(u64 v, float& lo, float& hi) {
    unsigned int a, b;
    asm("mov.b64 {%0, %1}, %2;" : "=r"(a), "=r"(b) : "l"(v));
    lo = __uint_as_float(a);
    hi = __uint_as_float(b);
}

// Folded lower-triangular S, row i padded to a multiple of 4 floats (zeros).
__host__ __device__ constexpr int rowLen(int i) { return (i + 4) & ~3; }
__host__ __device__ constexpr int rowOff(int i) {
    int s = 0;
    for (int t = 0; t < i; t++) s += rowLen(t);
    return s;
}
template <int D>
__host__ __device__ constexpr int triTot() { return rowOff(D); }

constexpr int TRI_O_F = triTot<D_O>();        // 1248 floats
constexpr int TRI_H_F = triTot<D_H>();        // 160 floats
constexpr int TOT_F   = TRI_O_F + TRI_H_F;    // 1408 floats (5632 B)
constexpr int BASE_O_Q = 0;                   // ulonglong2 index of O region
constexpr int BASE_H_Q = TRI_O_F / 4;         // 312

// Scratch (device global, written by prep kernel) and the constant-space copy.
__device__ float g_sfold[TOT_F];
__constant__ ulonglong2 cS[TOT_F / 4];        // 352 entries

// Prep: thread i<48 folds O row i; thread 64+i (i<16) folds H row i.
__global__ void prepS(const float* __restrict__ S_H,
                      const float* __restrict__ S_O) {
    const int t = threadIdx.x;
    if (t < D_O) {
        const int off = rowOff(t);
        for (int j = 0; j < t; j++) g_sfold[off + j] = 2.0f * S_O[t * D_O + j];
        g_sfold[off + t] = S_O[t * D_O + t];
        for (int j = t + 1; j < rowLen(t); j++) g_sfold[off + j] = 0.0f;
    } else if (t >= 64 && t - 64 < D_H) {
        const int i = t - 64;
        const int off = TRI_O_F + rowOff(i);
        for (int j = 0; j < i; j++) g_sfold[off + j] = 2.0f * S_H[i * D_H + j];
        g_sfold[off + i] = S_H[i * D_H + i];
        for (int j = i + 1; j < rowLen(i); j++) g_sfold[off + j] = 0.0f;
    }
}

// Warp = 1 atom, lane = channel; rows packed in pairs into u64.
// S is read from CONSTANT memory (warp-uniform addresses -> constant-port
// broadcast), keeping the L1/shared port free for the LDG/STG stream.
template <int D, int BASEQ>
__device__ __forceinline__ void processAtom(const float* __restrict__ x,
                                            float* __restrict__ out,
                                            int baseRow, int lane) {
    constexpr int KP = D / 2;
    const float* xp = x + (size_t)baseRow * C + lane;

    u64 y2[KP];
#pragma unroll
    for (int k = 0; k < KP; k++) {
        float a = __ldg(xp + (2 * k + 0) * C);
        float b = __ldg(xp + (2 * k + 1) * C);
        y2[k] = pack2(a, b);
    }

    u64 accA = 0ull, accB = 0ull;
#pragma unroll
    for (int k = 0; k < KP; k++) {
        const int i0 = 2 * k;
        const int nc = k / 2 + 1;                    // 16B chunks per row
        const int q0 = BASEQ + (rowOff(i0) >> 2);    // compile-time constants
        const int q1 = BASEQ + (rowOff(i0 + 1) >> 2);

        // even row 2k
        u64 e0 = 0ull, e1 = 0ull;
#pragma unroll
        for (int jc = 0; jc < nc; jc++) {
            ulonglong2 a = cS[q0 + jc];              // LDC.128 broadcast
            e0 = fma2(a.x, y2[2 * jc + 0], e0);
            e1 = fma2(a.y, y2[2 * jc + 1], e1);
        }
        float el, eh;
        unpack2(add2(e0, e1), el, eh);

        // odd row 2k+1
        u64 o0 = 0ull, o1 = 0ull;
#pragma unroll
        for (int jc = 0; jc < nc; jc++) {
            ulonglong2 b = cS[q1 + jc];
            o0 = fma2(b.x, y2[2 * jc + 0], o0);
            o1 = fma2(b.y, y2[2 * jc + 1], o1);
        }
        float ol, oh;
        unpack2(add2(o0, o1), ol, oh);

        if (k & 1)
            accB = fma2(y2[k], pack2(el + eh, ol + oh), accB);
        else
            accA = fma2(y2[k], pack2(el + eh, ol + oh), accA);
    }

    float alo, ahi;
    unpack2(add2(accA, accB), alo, ahi);
    const float inv  = 1.0f / (sqrtf(alo + ahi) + 1e-6f);
    const u64   inv2 = pack2(inv, inv);

    float* op = out + (size_t)baseRow * C + lane;
#pragma unroll
    for (int k = 0; k < KP; k++) {
        u64 m = mul2(y2[k], inv2);
        float s0, s1;
        unpack2(m, s0, s1);
        op[(2 * k + 0) * C] = s0;
        op[(2 * k + 1) * C] = s1;
    }
}

// Fused: every 3rd block is an O block, the other two are H blocks (1:2 mix
// per SM). No shared memory, no fill, no block-level sync.
__global__ __launch_bounds__(BLOCK, 4) void l2norm_fused(
    const float* __restrict__ x,
    const int* __restrict__ idx_H, const int* __restrict__ idx_O,
    float* __restrict__ out) {
    const int warp = threadIdx.x >> 5;
    const int lane = threadIdx.x & 31;
    const int bid  = blockIdx.x;
    const int q    = bid / 3;
    const int r    = bid - 3 * q;

    if (r == 0) {
        const int atom = q * WPB + warp;
        const int baseRow = __ldg(idx_O + atom * D_O);
        processAtom<D_O, BASE_O_Q>(x, out, baseRow, lane);
    } else {
        const int atom = (2 * q + (r - 1)) * WPB + warp;
        const int baseRow = __ldg(idx_H + atom * D_H);
        processAtom<D_H, BASE_H_Q>(x, out, baseRow, lane);
    }
}

extern "C" void kernel_launch(void* const* d_in, const int* in_sizes, int n_in,
                              void* d_out, int out_size) {
    const float* x     = (const float*)d_in[0];
    const float* S_H   = (const float*)d_in[1];
    const float* S_O   = (const float*)d_in[2];
    const int*   idx_H = (const int*)d_in[3];
    const int*   idx_O = (const int*)d_in[4];
    float* out = (float*)d_out;

    // 1) fold S into device scratch, 2) D2D copy into constant bank,
    // 3) main kernel. All graph-capturable (kernel, memcpy node, kernel).
    prepS<<<1, 256>>>(S_H, S_O);

    void* scratchPtr = nullptr;
    cudaGetSymbolAddress(&scratchPtr, g_sfold);
    cudaMemcpyToSymbolAsync(cS, scratchPtr, TOT_F * sizeof(float), 0,
                            cudaMemcpyDeviceToDevice, 0);

    l2norm_fused<<<NB, BLOCK>>>(x, idx_H, idx_O, out);
}